// round 1
// baseline (speedup 1.0000x reference)
#include <cuda_runtime.h>
#include <cstdint>

#define NPTS     16384
#define NCHUNK   16
#define CHUNK    (NPTS / NCHUNK)      // 1024 B points per chunk
#define ATILES   16
#define APERTILE (NPTS / ATILES)      // 1024 A points per tile
#define KA       4
#define THREADS  256

// ---------------- scratch (no allocations allowed) ----------------
__device__ __align__(16) float g_px[2][NPTS];   // -2*x   [0]=pred, [1]=target
__device__ __align__(16) float g_py[2][NPTS];   // -2*y
__device__ __align__(16) float g_pz[2][NPTS];   // -2*z
__device__ __align__(16) float g_c [2][NPTS];   // |p|^2
__device__ float g_scratch[2][NCHUNK][NPTS];    // per-chunk partial min scores
__device__ float g_sum[2];

// ---------------- packed f32x2 helpers ----------------
__device__ __forceinline__ unsigned long long pack2(float lo, float hi) {
    unsigned long long r;
    asm("mov.b64 %0, {%1, %2};" : "=l"(r) : "f"(lo), "f"(hi));
    return r;
}
__device__ __forceinline__ unsigned long long fma2(unsigned long long a,
                                                   unsigned long long b,
                                                   unsigned long long c) {
    unsigned long long d;
    asm("fma.rn.f32x2 %0, %1, %2, %3;" : "=l"(d) : "l"(a), "l"(b), "l"(c));
    return d;
}
__device__ __forceinline__ void unpack2(unsigned long long v, float& lo, float& hi) {
    asm("mov.b64 {%0, %1}, %2;" : "=f"(lo), "=f"(hi) : "l"(v));
}

#define POS_INF __int_as_float(0x7f800000)

// ---------------- kernel 1: pack coords, zero accumulators ----------------
__global__ void prep_kernel(const float* __restrict__ pred,
                            const float* __restrict__ targ) {
    int i = blockIdx.x * blockDim.x + threadIdx.x;
    if (i < 2) g_sum[i] = 0.0f;
    if (i >= 2 * NPTS) return;
    int s = i / NPTS;
    int j = i - s * NPTS;
    const float* src = s ? targ : pred;
    float x = src[3 * j + 0];
    float y = src[3 * j + 1];
    float z = src[3 * j + 2];
    g_px[s][j] = -2.0f * x;
    g_py[s][j] = -2.0f * y;
    g_pz[s][j] = -2.0f * z;
    g_c [s][j] = x * x + y * y + z * z;
}

// ---------------- kernel 2: main pairwise min-score ----------------
// grid = 2 * ATILES * NCHUNK = 512 blocks of 256 threads.
// block -> (dir, a_tile, chunk). Each thread owns KA=4 A points, loops over
// the CHUNK B points staged in shared memory. 2 B points per packed f32x2.
__global__ void __launch_bounds__(THREADS)
main_kernel(const float* __restrict__ pred, const float* __restrict__ targ) {
    __shared__ __align__(16) float sB[4][CHUNK];   // bx', by', bz', c  (16 KB)

    int bid    = blockIdx.x;
    int dir    = bid >> 8;        // 0: A=pred,B=targ   1: A=targ,B=pred
    int rem    = bid & 255;
    int a_tile = rem >> 4;
    int chunk  = rem & 15;
    int bset   = 1 - dir;
    int jbase  = chunk * CHUNK;

    // stage B chunk: 4 arrays x 1024 floats
    for (int t = threadIdx.x; t < CHUNK / 4; t += THREADS) {
        ((float4*)sB[0])[t] = ((const float4*)(g_px[bset] + jbase))[t];
        ((float4*)sB[1])[t] = ((const float4*)(g_py[bset] + jbase))[t];
        ((float4*)sB[2])[t] = ((const float4*)(g_pz[bset] + jbase))[t];
        ((float4*)sB[3])[t] = ((const float4*)(g_c [bset] + jbase))[t];
    }

    // load A points (raw coords), replicate into both packed halves
    const float* araw = dir ? targ : pred;
    int a0 = a_tile * APERTILE + threadIdx.x;

    unsigned long long ax2[KA], ay2[KA], az2[KA];
    float mlo[KA], mhi[KA];
#pragma unroll
    for (int k = 0; k < KA; k++) {
        int ai = a0 + k * THREADS;
        float x = araw[3 * ai + 0];
        float y = araw[3 * ai + 1];
        float z = araw[3 * ai + 2];
        ax2[k] = pack2(x, x);
        ay2[k] = pack2(y, y);
        az2[k] = pack2(z, z);
        mlo[k] = POS_INF;
        mhi[k] = POS_INF;
    }
    __syncthreads();

    // inner loop: 4 B points per iteration (2 packed f32x2 pairs)
    for (int j = 0; j < CHUNK; j += 4) {
        ulonglong2 vx = *(const ulonglong2*)&sB[0][j];
        ulonglong2 vy = *(const ulonglong2*)&sB[1][j];
        ulonglong2 vz = *(const ulonglong2*)&sB[2][j];
        ulonglong2 vc = *(const ulonglong2*)&sB[3][j];
#pragma unroll
        for (int k = 0; k < KA; k++) {
            unsigned long long s01 =
                fma2(ax2[k], vx.x, fma2(ay2[k], vy.x, fma2(az2[k], vz.x, vc.x)));
            unsigned long long s23 =
                fma2(ax2[k], vx.y, fma2(ay2[k], vy.y, fma2(az2[k], vz.y, vc.y)));
            float s0, s1, s2, s3;
            unpack2(s01, s0, s1);
            unpack2(s23, s2, s3);
            mlo[k] = fminf(mlo[k], fminf(s0, s2));
            mhi[k] = fminf(mhi[k], fminf(s1, s3));
        }
    }

#pragma unroll
    for (int k = 0; k < KA; k++) {
        int ai = a0 + k * THREADS;
        g_scratch[dir][chunk][ai] = fminf(mlo[k], mhi[k]);
    }
}

// ---------------- kernel 3: per-point reduce + sqrt + sum ----------------
// 128 blocks x 256 threads; blocks [0,64) = dir 0, [64,128) = dir 1.
__global__ void reduce_kernel() {
    int dir = blockIdx.x >> 6;
    int a   = (blockIdx.x & 63) * 256 + threadIdx.x;

    float m = POS_INF;
#pragma unroll
    for (int c = 0; c < NCHUNK; c++) m = fminf(m, g_scratch[dir][c][a]);

    float d = sqrtf(fmaxf(g_c[dir][a] + m, 0.0f));

    __shared__ float red[256];
    red[threadIdx.x] = d;
    __syncthreads();
    for (int s = 128; s > 0; s >>= 1) {
        if (threadIdx.x < s) red[threadIdx.x] += red[threadIdx.x + s];
        __syncthreads();
    }
    if (threadIdx.x == 0) atomicAdd(&g_sum[dir], red[0]);
}

// ---------------- kernel 4: finalize ----------------
__global__ void finalize_kernel(float* out) {
    out[0] = (g_sum[0] + g_sum[1]) * (1.0f / (float)NPTS);
}

// ---------------- launch ----------------
extern "C" void kernel_launch(void* const* d_in, const int* in_sizes, int n_in,
                              void* d_out, int out_size) {
    const float* pred = (const float*)d_in[0];
    const float* targ = (const float*)d_in[1];
    float* out = (float*)d_out;

    prep_kernel<<<(2 * NPTS + 255) / 256, 256>>>(pred, targ);
    main_kernel<<<2 * ATILES * NCHUNK, THREADS>>>(pred, targ);
    reduce_kernel<<<128, 256>>>();
    finalize_kernel<<<1, 1>>>(out);
}

// round 4
// speedup vs baseline: 1.1315x; 1.1315x over previous
#include <cuda_runtime.h>
#include <cstdint>

#define NPTS     16384
#define ATILES   16
#define APERTILE 1024                 // A points per tile = THREADS * KA
#define NCHUNK   32
#define CHUNK    512                  // B points staged per block
#define THREADS  256
#define KA       4
#define RBLOCKS  128                  // reduce-kernel blocks

// ---------------- persistent scratch (no allocations allowed) ----------------
__device__ float g_scratch[2][NCHUNK][NPTS];   // per-chunk partial min scores
__device__ float g_partial[RBLOCKS];           // per-reduce-block distance sums

// ---------------- packed f32x2 helpers ----------------
__device__ __forceinline__ unsigned long long pack2(float lo, float hi) {
    unsigned long long r;
    asm("mov.b64 %0, {%1, %2};" : "=l"(r) : "f"(lo), "f"(hi));
    return r;
}
__device__ __forceinline__ unsigned long long fma2(unsigned long long a,
                                                   unsigned long long b,
                                                   unsigned long long c) {
    unsigned long long d;
    asm("fma.rn.f32x2 %0, %1, %2, %3;" : "=l"(d) : "l"(a), "l"(b), "l"(c));
    return d;
}
__device__ __forceinline__ void unpack2(unsigned long long v, float& lo, float& hi) {
    asm("mov.b64 {%0, %1}, %2;" : "=f"(lo), "=f"(hi) : "l"(v));
}

#define POS_INF __int_as_float(0x7f800000)

// ---------------- kernel 1: main pairwise min-score ----------------
// grid = 2 dirs x 16 A-tiles x 32 B-chunks = 1024 blocks, 256 threads.
// Each thread owns KA=4 A points; block stages+packs its 512-point B chunk
// into shared memory, then scans it with packed f32x2 FMA chains.
__global__ void __launch_bounds__(THREADS)
main_kernel(const float* __restrict__ pred, const float* __restrict__ targ) {
    __shared__ __align__(16) float sB[4][CHUNK];    // bx', by', bz', |b|^2 (8 KB)

    const int bid    = blockIdx.x;
    const int dir    = bid >> 9;          // 0: A=pred,B=targ   1: A=targ,B=pred
    const int rem    = bid & 511;
    const int a_tile = rem >> 5;
    const int chunk  = rem & 31;
    const int tid    = threadIdx.x;

    const float* __restrict__ araw = dir ? targ : pred;
    const float* __restrict__ braw = dir ? pred : targ;
    const int jbase = chunk * CHUNK;

    // ---- stage + pack B chunk from raw coords ----
    for (int p = tid; p < CHUNK; p += THREADS) {
        const int j = jbase + p;
        float x = braw[3 * j + 0];
        float y = braw[3 * j + 1];
        float z = braw[3 * j + 2];
        sB[0][p] = -2.0f * x;
        sB[1][p] = -2.0f * y;
        sB[2][p] = -2.0f * z;
        sB[3][p] = x * x + y * y + z * z;
    }

    // ---- load A points, replicate into both packed halves ----
    const int a0 = a_tile * APERTILE + tid;
    unsigned long long ax2[KA], ay2[KA], az2[KA];
    float mlo[KA], mhi[KA];
#pragma unroll
    for (int k = 0; k < KA; k++) {
        const int ai = a0 + k * THREADS;
        float x = araw[3 * ai + 0];
        float y = araw[3 * ai + 1];
        float z = araw[3 * ai + 2];
        ax2[k] = pack2(x, x);
        ay2[k] = pack2(y, y);
        az2[k] = pack2(z, z);
        mlo[k] = POS_INF;
        mhi[k] = POS_INF;
    }
    __syncthreads();

    // ---- main loop: 4 B points per iteration (2 packed f32x2 lanes) ----
    for (int j = 0; j < CHUNK; j += 4) {
        ulonglong2 vx = *(const ulonglong2*)&sB[0][j];
        ulonglong2 vy = *(const ulonglong2*)&sB[1][j];
        ulonglong2 vz = *(const ulonglong2*)&sB[2][j];
        ulonglong2 vc = *(const ulonglong2*)&sB[3][j];
#pragma unroll
        for (int k = 0; k < KA; k++) {
            unsigned long long s01 =
                fma2(ax2[k], vx.x, fma2(ay2[k], vy.x, fma2(az2[k], vz.x, vc.x)));
            unsigned long long s23 =
                fma2(ax2[k], vx.y, fma2(ay2[k], vy.y, fma2(az2[k], vz.y, vc.y)));
            float s0, s1, s2, s3;
            unpack2(s01, s0, s1);
            unpack2(s23, s2, s3);
            mlo[k] = fminf(mlo[k], fminf(s0, s2));
            mhi[k] = fminf(mhi[k], fminf(s1, s3));
        }
    }

#pragma unroll
    for (int k = 0; k < KA; k++) {
        g_scratch[dir][chunk][a0 + k * THREADS] = fminf(mlo[k], mhi[k]);
    }
}

// ---------------- kernel 2: per-point reduce + sqrt + block partials ----------
// 128 blocks x 256 threads; blocks [0,64) = dir 0, [64,128) = dir 1.
// Each block handles 256 A points; writes one partial sum (no atomics).
__global__ void __launch_bounds__(THREADS)
reduce_kernel(const float* __restrict__ pred, const float* __restrict__ targ) {
    const int dir = blockIdx.x >> 6;
    const int a   = (blockIdx.x & 63) * THREADS + threadIdx.x;
    const float* __restrict__ araw = dir ? targ : pred;

    float m = POS_INF;
#pragma unroll
    for (int c = 0; c < NCHUNK; c++) m = fminf(m, g_scratch[dir][c][a]);

    float x = araw[3 * a + 0];
    float y = araw[3 * a + 1];
    float z = araw[3 * a + 2];
    float ca = x * x + y * y + z * z;
    float d = sqrtf(fmaxf(ca + m, 0.0f));

    // block reduction
    __shared__ float sRed[THREADS / 32];
#pragma unroll
    for (int s = 16; s > 0; s >>= 1)
        d += __shfl_xor_sync(0xFFFFFFFFu, d, s);
    if ((threadIdx.x & 31) == 0) sRed[threadIdx.x >> 5] = d;
    __syncthreads();
    if (threadIdx.x == 0) {
        float t = 0.0f;
#pragma unroll
        for (int w = 0; w < THREADS / 32; w++) t += sRed[w];
        g_partial[blockIdx.x] = t;
    }
}

// ---------------- kernel 3: final sum ----------------
__global__ void final_kernel(float* __restrict__ out) {
    float v = (threadIdx.x < RBLOCKS) ? g_partial[threadIdx.x] : 0.0f;
#pragma unroll
    for (int s = 16; s > 0; s >>= 1)
        v += __shfl_xor_sync(0xFFFFFFFFu, v, s);
    __shared__ float sRed[4];
    if ((threadIdx.x & 31) == 0) sRed[threadIdx.x >> 5] = v;
    __syncthreads();
    if (threadIdx.x == 0) {
        out[0] = (sRed[0] + sRed[1] + sRed[2] + sRed[3]) * (1.0f / (float)NPTS);
    }
}

// ---------------- launch ----------------
extern "C" void kernel_launch(void* const* d_in, const int* in_sizes, int n_in,
                              void* d_out, int out_size) {
    const float* pred = (const float*)d_in[0];
    const float* targ = (const float*)d_in[1];
    float* out = (float*)d_out;

    main_kernel<<<2 * ATILES * NCHUNK, THREADS>>>(pred, targ);
    reduce_kernel<<<RBLOCKS, THREADS>>>(pred, targ);
    final_kernel<<<1, RBLOCKS>>>(out);
}